// round 2
// baseline (speedup 1.0000x reference)
#include <cuda_runtime.h>
#include <cstdint>

// Reference math reduces to an all-zero output:
//   probs = one-hot at basis-state 0; gather indices 1<<q never hit index 0
//   -> projected features are exactly 0 -> p1 @ p2^T == 0.
// Kernel = pure 256 MB zero-fill of d_out. HBM-write-bound.
//
// R1 showed DRAM=71%, occ=22.5%, issue=21.3% with 1 store/thread:
// issue/scheduling-starved. R2: 16 float4 stores per thread (grid-stride,
// coalesced), 4096 blocks, streaming (__stcs) stores.

#ifndef UNROLL_ITERS
#define UNROLL_ITERS 16
#endif

__global__ void zero_fill_fast(float4* __restrict__ out) {
    const size_t stride = (size_t)gridDim.x * blockDim.x;
    size_t i = (size_t)blockIdx.x * blockDim.x + threadIdx.x;
    const float4 z = make_float4(0.0f, 0.0f, 0.0f, 0.0f);
#pragma unroll
    for (int k = 0; k < UNROLL_ITERS; ++k) {
        __stcs(&out[i], z);
        i += stride;
    }
}

__global__ void zero_fill_generic(float4* __restrict__ out, size_t n4) {
    const size_t stride = (size_t)gridDim.x * blockDim.x;
    const float4 z = make_float4(0.0f, 0.0f, 0.0f, 0.0f);
    for (size_t i = (size_t)blockIdx.x * blockDim.x + threadIdx.x; i < n4;
         i += stride) {
        __stcs(&out[i], z);
    }
}

__global__ void zero_fill_tail(float* __restrict__ out, size_t start, size_t n) {
    size_t i = start + (size_t)blockIdx.x * blockDim.x + threadIdx.x;
    if (i < n) out[i] = 0.0f;
}

extern "C" void kernel_launch(void* const* d_in, const int* in_sizes, int n_in,
                              void* d_out, int out_size) {
    (void)d_in; (void)in_sizes; (void)n_in;

    float* out = (float*)d_out;
    size_t n  = (size_t)out_size;   // 8192*8192 = 67,108,864 floats
    size_t n4 = n / 4;              // 16,777,216 float4 stores

    const int threads = 256;
    const size_t per_block = (size_t)threads * UNROLL_ITERS;  // 4096

    if (n4 > 0) {
        if (n4 % per_block == 0) {
            unsigned blocks = (unsigned)(n4 / per_block);     // 4096
            zero_fill_fast<<<blocks, threads>>>((float4*)out);
        } else {
            unsigned blocks = (unsigned)((n4 + per_block - 1) / per_block);
            zero_fill_generic<<<blocks, threads>>>((float4*)out, n4);
        }
    }

    size_t tail_start = n4 * 4;
    if (tail_start < n) {
        size_t tail = n - tail_start;
        unsigned blocks = (unsigned)((tail + 127) / 128);
        zero_fill_tail<<<blocks, 128>>>(out, tail_start, n);
    }
}